// round 3
// baseline (speedup 1.0000x reference)
#include <cuda_runtime.h>
#include <cuda_bf16.h>
#include <math.h>

typedef unsigned int u32;

#define BB   256
#define TT   512
#define HH   256
#define LL   4

#define NBLK 128
#define NTHR 256
#define NBAR (LL * TT)

// smem strides (in 32-bit words)
#define AS   132   // A (weights) row stride: 128 k-pair words + 4 pad (conflict-free frag loads)
#define BS   40    // B (h) row stride: 32 batch + 8 pad (conflict-free frag loads)
#define GS   33    // gate smem row stride

// smem layout sizes (words)
#define SZ_A (64 * AS)        // 8448
#define SZ_B (128 * BS)       // 5120
#define SZ_G (64 * GS)        // 2112
#define SMEM_WORDS (2 * SZ_A + 2 * SZ_B + SZ_G + 64 + 64)
#define SMEM_BYTES (SMEM_WORDS * 4)

// ---------------- device scratch (allocation-free rule) ----------------
// h sequences, packed bf16 pairs: word (t, k2, b) = {h[2k2], h[2k2+1]} for batch b
__device__ __align__(128) u32 g_hAhi[TT * 128 * BB];
__device__ __align__(128) u32 g_hAlo[TT * 128 * BB];
__device__ __align__(128) u32 g_hBhi[TT * 128 * BB];
__device__ __align__(128) u32 g_hBlo[TT * 128 * BB];
// per-block input-projection gates, fp32: [block][t][64 m][32 n]
__device__ __align__(128) float g_gih[(size_t)NBLK * TT * 64 * 32];
__device__ unsigned g_bar[NBAR];

struct Params {
    const float* x;
    const float* Wih[LL];
    const float* Whh[LL];
    const float* bih[LL];
    const float* bhh[LL];
    const float* fcW;
    const float* fcb;
    float* out;
};

// ---------------- helpers ----------------
__device__ __forceinline__ float sigf(float v) {
    return __fdividef(1.0f, 1.0f + __expf(-v));
}
__device__ __forceinline__ float tanhfast(float v) {
    return 1.0f - __fdividef(2.0f, __expf(2.0f * v) + 1.0f);
}

__device__ __forceinline__ void split_pack(float x, float y, u32& hi, u32& lo) {
    __nv_bfloat162 h2, l2;
    h2.x = __float2bfloat16_rn(x);
    h2.y = __float2bfloat16_rn(y);
    l2.x = __float2bfloat16_rn(x - __bfloat162float(h2.x));
    l2.y = __float2bfloat16_rn(y - __bfloat162float(h2.y));
    hi = *reinterpret_cast<u32*>(&h2);
    lo = *reinterpret_cast<u32*>(&l2);
}

__device__ __forceinline__ void mma16816(float c[4], u32 a0, u32 a1, u32 a2, u32 a3,
                                         u32 b0, u32 b1) {
    asm("mma.sync.aligned.m16n8k16.row.col.f32.bf16.bf16.f32 "
        "{%0,%1,%2,%3}, {%4,%5,%6,%7}, {%8,%9}, {%0,%1,%2,%3};"
        : "+f"(c[0]), "+f"(c[1]), "+f"(c[2]), "+f"(c[3])
        : "r"(a0), "r"(a1), "r"(a2), "r"(a3), "r"(b0), "r"(b1));
}

// full K=256 warp-tile MMA: accum c[2][4] over sA(hi/lo) x sB(hi/lo), 3 split passes
__device__ __forceinline__ void mma_tile(const u32* __restrict__ sAhi, const u32* __restrict__ sAlo,
                                         const u32* __restrict__ sBhi, const u32* __restrict__ sBlo,
                                         int mb, int wn, int lr, int lc, float c[2][4]) {
    #pragma unroll 4
    for (int kk = 0; kk < 16; ++kk) {
        const int ab = kk * 8 + lc;
        const u32 ah0 = sAhi[(mb + lr) * AS + ab];
        const u32 ah1 = sAhi[(mb + 8 + lr) * AS + ab];
        const u32 ah2 = sAhi[(mb + lr) * AS + ab + 4];
        const u32 ah3 = sAhi[(mb + 8 + lr) * AS + ab + 4];
        const u32 al0 = sAlo[(mb + lr) * AS + ab];
        const u32 al1 = sAlo[(mb + 8 + lr) * AS + ab];
        const u32 al2 = sAlo[(mb + lr) * AS + ab + 4];
        const u32 al3 = sAlo[(mb + 8 + lr) * AS + ab + 4];
        #pragma unroll
        for (int nb = 0; nb < 2; ++nb) {
            const int col = wn * 16 + nb * 8 + lr;
            const u32 bh0 = sBhi[(kk * 8 + lc) * BS + col];
            const u32 bh1 = sBhi[(kk * 8 + 4 + lc) * BS + col];
            const u32 bl0 = sBlo[(kk * 8 + lc) * BS + col];
            const u32 bl1 = sBlo[(kk * 8 + 4 + lc) * BS + col];
            mma16816(c[nb], ah0, ah1, ah2, ah3, bh0, bh1);   // hi*hi
            mma16816(c[nb], ah0, ah1, ah2, ah3, bl0, bl1);   // hi*lo
            mma16816(c[nb], al0, al1, al2, al3, bh0, bh1);   // lo*hi
        }
    }
}

__device__ __forceinline__ void grid_bar(int slot) {
    __syncthreads();
    if (threadIdx.x == 0) {
        __threadfence();
        atomicAdd(&g_bar[slot], 1u);
        while (((volatile unsigned*)g_bar)[slot] < (unsigned)NBLK) { }
        __threadfence();
    }
    __syncthreads();
}

// convert W rows for this block into smem as bf16 hi/lo k-pairs. caller syncs.
__device__ __forceinline__ void load_W(const float* __restrict__ W, int j0,
                                       u32* __restrict__ sAhi, u32* __restrict__ sAlo) {
    for (int i = threadIdx.x; i < 64 * 128; i += NTHR) {
        const int m = i >> 7;
        const int k2 = i & 127;
        const int row = (m >> 4) * HH + j0 + (m & 15);
        const float2 w = *(const float2*)(W + (size_t)row * HH + 2 * k2);
        split_pack(w.x, w.y, sAhi[m * AS + k2], sAlo[m * AS + k2]);
    }
}

// load h tile (k2 0..127, batch b0..b0+31) from global packed buffers into smem. caller syncs.
__device__ __forceinline__ void load_B(const u32* __restrict__ ghi, const u32* __restrict__ glo,
                                       int t, int b0,
                                       u32* __restrict__ sBhi, u32* __restrict__ sBlo) {
    const u32* bh = ghi + (size_t)t * 128 * BB + b0;
    const u32* bl = glo + (size_t)t * 128 * BB + b0;
    for (int i = threadIdx.x; i < 128 * 32; i += NTHR) {
        const int k2 = i >> 5;
        const int bb = i & 31;
        sBhi[k2 * BS + bb] = bh[k2 * BB + bb];
        sBlo[k2 * BS + bb] = bl[k2 * BB + bb];
    }
}

// ---------------- kernel ----------------
__global__ void __launch_bounds__(NTHR, 1) lstm_mma(Params p) {
    extern __shared__ u32 smem[];
    u32*   sAhi = smem;
    u32*   sAlo = sAhi + SZ_A;
    u32*   sBhi = sAlo + SZ_A;
    u32*   sBlo = sBhi + SZ_B;
    float* gsm  = (float*)(sBlo + SZ_B);
    float* bs   = gsm + SZ_G;
    float* wxs  = bs + 64;

    const int tid = threadIdx.x;
    const int bid = blockIdx.x;
    const int jt  = bid >> 3;          // 0..15
    const int bt  = bid & 7;           // 0..7
    const int j0  = jt * 16;
    const int b0  = bt * 32;

    const int wid = tid >> 5;
    const int lane = tid & 31;
    const int lr = lane >> 2;          // 0..7
    const int lc = lane & 3;           // 0..3
    const int mb = (wid >> 1) * 16;    // warp m-base
    const int wn = wid & 1;            // warp n-half

    float* gG0 = g_gih + (size_t)bid * TT * 2048;

    int slot = 0;

    for (int l = 0; l < LL; ++l) {
        // bias (+ rank-1 input weight for layer 0)
        if (tid < 64) {
            const int row = (tid >> 4) * HH + j0 + (tid & 15);
            bs[tid] = p.bih[l][row] + p.bhh[l][row];
            if (l == 0) wxs[tid] = p.Wih[0][row];   // W_ih0 is [4H,1]
        }
        __syncthreads();

        const u32* inhi = (l & 1) ? g_hAhi : g_hBhi;
        const u32* inlo = (l & 1) ? g_hAlo : g_hBlo;
        u32* outhi = (l & 1) ? g_hBhi : g_hAhi;
        u32* outlo = (l & 1) ? g_hBlo : g_hAlo;

        // ---- phase 1: input projections for all t (no cross-block deps) ----
        if (l == 0) {
            for (int idx = tid; idx < 2048; idx += NTHR) {
                const int m = idx >> 5;
                const int n = idx & 31;
                const float wm = wxs[m];
                const float bm = bs[m];
                const float* xr = p.x + (size_t)(b0 + n) * TT;
                float* gw = gG0 + idx;
                for (int t = 0; t < TT; ++t)
                    gw[(size_t)t * 2048] = fmaf(wm, xr[t], bm);
            }
        } else {
            load_W(p.Wih[l], j0, sAhi, sAlo);
            __syncthreads();
            for (int t = 0; t < TT; ++t) {
                __syncthreads();
                load_B(inhi, inlo, t, b0, sBhi, sBlo);
                __syncthreads();
                float c[2][4];
                #pragma unroll
                for (int nb = 0; nb < 2; ++nb) {
                    c[nb][0] = c[nb][1] = bs[mb + lr];
                    c[nb][2] = c[nb][3] = bs[mb + 8 + lr];
                }
                mma_tile(sAhi, sAlo, sBhi, sBlo, mb, wn, lr, lc, c);
                float* gw = gG0 + (size_t)t * 2048;
                #pragma unroll
                for (int nb = 0; nb < 2; ++nb) {
                    const int col = wn * 16 + nb * 8 + 2 * lc;
                    *(float2*)(gw + (mb + lr) * 32 + col)     = make_float2(c[nb][0], c[nb][1]);
                    *(float2*)(gw + (mb + 8 + lr) * 32 + col) = make_float2(c[nb][2], c[nb][3]);
                }
            }
        }
        __syncthreads();

        // ---- phase 2: sequential recurrence ----
        load_W(p.Whh[l], j0, sAhi, sAlo);
        __syncthreads();

        // per-thread cell state: thread owns hidden pair (2jp, 2jp+1) x batch bb
        const int jp = tid >> 5;       // 0..7
        const int bb = tid & 31;       // 0..31
        float cc0 = 0.f, cc1 = 0.f;

        for (int t = 0; t < TT; ++t) {
            if (t > 0) {
                __syncthreads();
                load_B(outhi, outlo, t - 1, b0, sBhi, sBlo);
                __syncthreads();
            }
            float c[2][4];
            {   // init accumulators from precomputed input gates
                const float* gw = gG0 + (size_t)t * 2048;
                #pragma unroll
                for (int nb = 0; nb < 2; ++nb) {
                    const int col = wn * 16 + nb * 8 + 2 * lc;
                    const float2 c01 = *(const float2*)(gw + (mb + lr) * 32 + col);
                    const float2 c23 = *(const float2*)(gw + (mb + 8 + lr) * 32 + col);
                    c[nb][0] = c01.x; c[nb][1] = c01.y;
                    c[nb][2] = c23.x; c[nb][3] = c23.y;
                }
            }
            if (t > 0)
                mma_tile(sAhi, sAlo, sBhi, sBlo, mb, wn, lr, lc, c);

            // dump gates to smem
            #pragma unroll
            for (int nb = 0; nb < 2; ++nb) {
                const int col = wn * 16 + nb * 8 + 2 * lc;
                gsm[(mb + lr) * GS + col]         = c[nb][0];
                gsm[(mb + lr) * GS + col + 1]     = c[nb][1];
                gsm[(mb + 8 + lr) * GS + col]     = c[nb][2];
                gsm[(mb + 8 + lr) * GS + col + 1] = c[nb][3];
            }
            __syncthreads();

            // elementwise LSTM cell for the owned pair
            {
                const int jl0 = 2 * jp, jl1 = 2 * jp + 1;
                const float ig0 = gsm[(jl0) * GS + bb];
                const float fg0 = gsm[(16 + jl0) * GS + bb];
                const float gg0 = gsm[(32 + jl0) * GS + bb];
                const float og0 = gsm[(48 + jl0) * GS + bb];
                const float ig1 = gsm[(jl1) * GS + bb];
                const float fg1 = gsm[(16 + jl1) * GS + bb];
                const float gg1 = gsm[(32 + jl1) * GS + bb];
                const float og1 = gsm[(48 + jl1) * GS + bb];

                cc0 = sigf(fg0) * cc0 + sigf(ig0) * tanhfast(gg0);
                cc1 = sigf(fg1) * cc1 + sigf(ig1) * tanhfast(gg1);
                const float h0 = sigf(og0) * tanhfast(cc0);
                const float h1 = sigf(og1) * tanhfast(cc1);

                u32 hiw, low;
                split_pack(h0, h1, hiw, low);
                const size_t widx = ((size_t)t * 128 + (j0 >> 1) + jp) * BB + b0 + bb;
                outhi[widx] = hiw;
                outlo[widx] = low;
            }
            grid_bar(slot++);
        }
        // reset cell state handled by re-init at next layer
    }

    // ---- final FC on h(T-1) of layer 3 (buffer B) + barrier reset ----
    if (bid == 0) {
        const int b = tid;  // 256 threads, 256 batch rows
        float acc = p.fcb[0];
        const u32* bh = g_hBhi + ((size_t)(TT - 1) * 128) * BB + b;
        const u32* bl = g_hBlo + ((size_t)(TT - 1) * 128) * BB + b;
        for (int k2 = 0; k2 < 128; ++k2) {
            const u32 hw = bh[k2 * BB];
            const u32 lw = bl[k2 * BB];
            const __nv_bfloat162 h2 = *reinterpret_cast<const __nv_bfloat162*>(&hw);
            const __nv_bfloat162 l2 = *reinterpret_cast<const __nv_bfloat162*>(&lw);
            const float h0 = __bfloat162float(h2.x) + __bfloat162float(l2.x);
            const float h1 = __bfloat162float(h2.y) + __bfloat162float(l2.y);
            const float2 w = *(const float2*)(p.fcW + 2 * k2);
            acc = fmaf(w.x, h0, fmaf(w.y, h1, acc));
        }
        p.out[b] = acc;
        for (int i = tid; i < NBAR; i += NTHR) g_bar[i] = 0;
    }
}

extern "C" void kernel_launch(void* const* d_in, const int* in_sizes, int n_in,
                              void* d_out, int out_size) {
    (void)in_sizes; (void)n_in; (void)out_size;
    Params p;
    p.x = (const float*)d_in[0];
    for (int l = 0; l < LL; ++l) {
        p.Wih[l] = (const float*)d_in[1 + 4 * l];
        p.Whh[l] = (const float*)d_in[2 + 4 * l];
        p.bih[l] = (const float*)d_in[3 + 4 * l];
        p.bhh[l] = (const float*)d_in[4 + 4 * l];
    }
    p.fcW = (const float*)d_in[17];
    p.fcb = (const float*)d_in[18];
    p.out = (float*)d_out;

    cudaFuncSetAttribute(lstm_mma, cudaFuncAttributeMaxDynamicSharedMemorySize, SMEM_BYTES);
    lstm_mma<<<NBLK, NTHR, SMEM_BYTES>>>(p);
}

// round 6
// speedup vs baseline: 2.1340x; 2.1340x over previous
#include <cuda_runtime.h>
#include <cuda_bf16.h>
#include <math.h>

typedef unsigned int u32;

#define BB   256
#define TT   512
#define HH   256
#define LL   4
#define NBLK 128
#define NTHR 256
#define GRP  16          // blocks per barrier group (same bt)

#define AS   132         // A row stride (words): 128 k2 + 4 pad
#define BSB  132         // B row stride (words): 128 k2 + 4 pad
#define GS   33          // gate smem row stride

#define SZ_A (64 * AS)   // 8448 words
#define SZ_B (32 * BSB)  // 4224 words
#define SZ_G (64 * GS)   // 2112 words

#define OFF_AHH_HI 0
#define OFF_AHH_LO (SZ_A)
#define OFF_AIH_HI (2 * SZ_A)
#define OFF_AIH_LO (3 * SZ_A)
#define OFF_B_HI   (4 * SZ_A)
#define OFF_B_LO   (4 * SZ_A + SZ_B)
#define OFF_G      (4 * SZ_A + 2 * SZ_B)
#define OFF_BSN    (OFF_G + SZ_G)
#define OFF_BS0    (OFF_BSN + 64)
#define OFF_WXS    (OFF_BS0 + 64)
#define OFF_XS     (OFF_WXS + 64)
#define SMEM_WORDS (OFF_XS + 32)
#define SMEM_BYTES (SMEM_WORDS * 4)   // ~178.3 KB

// ---------------- device scratch ----------------
// h sequences, batch-major packed bf16 pairs: word (t, b, k2) = {h[2k2], h[2k2+1]}
__device__ __align__(128) u32 g_hAhi[(size_t)TT * BB * 128];
__device__ __align__(128) u32 g_hAlo[(size_t)TT * BB * 128];
__device__ __align__(128) u32 g_hBhi[(size_t)TT * BB * 128];
__device__ __align__(128) u32 g_hBlo[(size_t)TT * BB * 128];
// per-block input-projection gates (incl. bias), fp32: [block][t][64 m][32 n]
__device__ __align__(128) float g_gih[(size_t)NBLK * TT * 2048];
__device__ unsigned g_bar[8 * LL * TT];   // per-group slots
__device__ unsigned g_fin;

struct Params {
    const float* x;
    const float* Wih[LL];
    const float* Whh[LL];
    const float* bih[LL];
    const float* bhh[LL];
    const float* fcW;
    const float* fcb;
    float* out;
};

// ---------------- helpers ----------------
__device__ __forceinline__ float sigf(float v) {
    return __fdividef(1.0f, 1.0f + __expf(-v));
}
__device__ __forceinline__ float tanhfast(float v) {
    return 1.0f - __fdividef(2.0f, __expf(2.0f * v) + 1.0f);
}

__device__ __forceinline__ void split_pack(float x, float y, u32& hi, u32& lo) {
    __nv_bfloat162 h2, l2;
    h2.x = __float2bfloat16_rn(x);
    h2.y = __float2bfloat16_rn(y);
    l2.x = __float2bfloat16_rn(x - __bfloat162float(h2.x));
    l2.y = __float2bfloat16_rn(y - __bfloat162float(h2.y));
    hi = *reinterpret_cast<u32*>(&h2);
    lo = *reinterpret_cast<u32*>(&l2);
}

__device__ __forceinline__ void mma16816(float c[4], u32 a0, u32 a1, u32 a2, u32 a3,
                                         u32 b0, u32 b1) {
    asm("mma.sync.aligned.m16n8k16.row.col.f32.bf16.bf16.f32 "
        "{%0,%1,%2,%3}, {%4,%5,%6,%7}, {%8,%9}, {%0,%1,%2,%3};"
        : "+f"(c[0]), "+f"(c[1]), "+f"(c[2]), "+f"(c[3])
        : "r"(a0), "r"(a1), "r"(a2), "r"(a3), "r"(b0), "r"(b1));
}

__device__ __forceinline__ void ldsm4(u32& r0, u32& r1, u32& r2, u32& r3, u32 addr) {
    asm volatile("ldmatrix.sync.aligned.m8n8.x4.shared.b16 {%0,%1,%2,%3}, [%4];"
                 : "=r"(r0), "=r"(r1), "=r"(r2), "=r"(r3) : "r"(addr));
}

// 8 consecutive k2-groups of the K dimension, 3-pass split accumulate
__device__ __forceinline__ void mma_k8(u32 aHi, u32 aLo, u32 bHiA, u32 bLoA,
                                       int k0, float c[2][4]) {
    #pragma unroll
    for (int kk = k0; kk < k0 + 8; ++kk) {
        u32 a0, a1, a2, a3, l0, l1, l2, l3;
        u32 b0, b1, b2, b3, m0, m1, m2, m3;
        ldsm4(a0, a1, a2, a3, aHi + kk * 32);
        ldsm4(l0, l1, l2, l3, aLo + kk * 32);
        ldsm4(b0, b1, b2, b3, bHiA + kk * 32);
        ldsm4(m0, m1, m2, m3, bLoA + kk * 32);
        mma16816(c[0], a0, a1, a2, a3, b0, b2);
        mma16816(c[1], a0, a1, a2, a3, b1, b3);
        mma16816(c[0], a0, a1, a2, a3, m0, m2);
        mma16816(c[1], a0, a1, a2, a3, m1, m3);
        mma16816(c[0], l0, l1, l2, l3, b0, b2);
        mma16816(c[1], l0, l1, l2, l3, b1, b3);
    }
}

__device__ __forceinline__ void mma_full(u32 aHi, u32 aLo, u32 bHiA, u32 bLoA,
                                         float c[2][4]) {
    float d[2][4] = {{0.f, 0.f, 0.f, 0.f}, {0.f, 0.f, 0.f, 0.f}};
    mma_k8(aHi, aLo, bHiA, bLoA, 0, c);
    mma_k8(aHi, aLo, bHiA, bLoA, 8, d);
    #pragma unroll
    for (int i = 0; i < 2; ++i)
        #pragma unroll
        for (int j = 0; j < 4; ++j) c[i][j] += d[i][j];
}

// hardened barrier: release-arrive via red.global, acquire-poll + nanosleep backoff
__device__ __forceinline__ void bar_arrive(unsigned* p) {
    __syncthreads();
    if (threadIdx.x == 0) {
        asm volatile("red.release.gpu.global.add.u32 [%0], %1;"
                     :: "l"(p), "r"(1u) : "memory");
    }
}
__device__ __forceinline__ void bar_wait(unsigned* p, unsigned target) {
    if (threadIdx.x == 0) {
        unsigned v;
        asm volatile("ld.acquire.gpu.global.u32 %0, [%1];" : "=r"(v) : "l"(p) : "memory");
        while (v < target) {
            __nanosleep(32);
            asm volatile("ld.acquire.gpu.global.u32 %0, [%1];" : "=r"(v) : "l"(p) : "memory");
        }
    }
    __syncthreads();
}

// convert 64xK weight rows into smem bf16 hi/lo k2-pair words
__device__ __forceinline__ void load_W(const float* __restrict__ W, int j0,
                                       u32* __restrict__ shi, u32* __restrict__ slo) {
    for (int i = threadIdx.x; i < 64 * 128; i += NTHR) {
        const int m = i >> 7;
        const int k2 = i & 127;
        const int row = (m >> 4) * HH + j0 + (m & 15);
        const float2 w = *(const float2*)(W + (size_t)row * HH + 2 * k2);
        split_pack(w.x, w.y, shi[m * AS + k2], slo[m * AS + k2]);
    }
}

// load h(t) tile for batch rows b0..b0+31: 4 rows per warp, LDG.128 + STS.128
__device__ __forceinline__ void load_B(const u32* __restrict__ ghi, const u32* __restrict__ glo,
                                       int t, int b0, u32* __restrict__ sBhi,
                                       u32* __restrict__ sBlo, int wid, int lane) {
    #pragma unroll
    for (int r = 0; r < 4; ++r) {
        const int bbr = 4 * wid + r;
        const size_t gi = ((size_t)t * BB + b0 + bbr) * 128 + lane * 4;
        const uint4 vh = *(const uint4*)(ghi + gi);
        const uint4 vl = *(const uint4*)(glo + gi);
        *(uint4*)(sBhi + bbr * BSB + lane * 4) = vh;
        *(uint4*)(sBlo + bbr * BSB + lane * 4) = vl;
    }
}

// ---------------- kernel ----------------
__global__ void __launch_bounds__(NTHR, 1) lstm_fused(Params p) {
    extern __shared__ u32 sm[];
    u32* sAhhHi = sm + OFF_AHH_HI;
    u32* sAhhLo = sm + OFF_AHH_LO;
    u32* sAihHi = sm + OFF_AIH_HI;
    u32* sAihLo = sm + OFF_AIH_LO;
    u32* sBhi   = sm + OFF_B_HI;
    u32* sBlo   = sm + OFF_B_LO;
    float* gsm  = (float*)(sm + OFF_G);
    float* bsn  = (float*)(sm + OFF_BSN);
    float* bs0  = (float*)(sm + OFF_BS0);
    float* wxs  = (float*)(sm + OFF_WXS);
    float* xs   = (float*)(sm + OFF_XS);

    const int tid  = threadIdx.x;
    const int bid  = blockIdx.x;
    const int jt   = bid >> 3;
    const int bt   = bid & 7;
    const int j0   = jt * 16;
    const int b0   = bt * 32;
    const int wid  = tid >> 5;
    const int lane = tid & 31;
    const int lr   = lane >> 2;
    const int lc   = lane & 3;
    const int mb   = (wid >> 1) * 16;
    const int wn   = wid & 1;
    const int jp   = tid & 7;        // hidden pair owned for elementwise
    const int bbx  = tid >> 3;       // batch col owned for elementwise

    // ldmatrix lane offsets (words)
    const u32 aoffw = (u32)((mb + ((lane >> 3) & 1) * 8 + (lane & 7)) * AS + (lane >> 4) * 4);
    const u32 boffw = (u32)((wn * 16 + ((lane >> 3) & 1) * 8 + (lane & 7)) * BSB + (lane >> 4) * 4);
    const u32 smbase = (u32)__cvta_generic_to_shared(sm);
    const u32 aHH_hi = smbase + (OFF_AHH_HI + aoffw) * 4;
    const u32 aHH_lo = smbase + (OFF_AHH_LO + aoffw) * 4;
    const u32 aIH_hi = smbase + (OFF_AIH_HI + aoffw) * 4;
    const u32 aIH_lo = smbase + (OFF_AIH_LO + aoffw) * 4;
    const u32 bAd_hi = smbase + (OFF_B_HI + boffw) * 4;
    const u32 bAd_lo = smbase + (OFF_B_LO + boffw) * 4;

    float* gG0 = g_gih + (size_t)bid * TT * 2048;
    unsigned* bars = g_bar + bt * (LL * TT);
    const int col0 = wn * 16 + 2 * lc;

    // initial staging: layer-0 Whh, layer-1 Wih, biases
    load_W(p.Whh[0], j0, sAhhHi, sAhhLo);
    load_W(p.Wih[1], j0, sAihHi, sAihLo);
    if (tid < 64) {
        const int row = (tid >> 4) * HH + j0 + (tid & 15);
        bs0[tid] = p.bih[0][row] + p.bhh[0][row];
        wxs[tid] = p.Wih[0][row];             // W_ih0 is [4H, 1]
        bsn[tid] = p.bih[1][row] + p.bhh[1][row];
    }
    __syncthreads();

    for (int l = 0; l < LL; ++l) {
        u32* outhi = (l & 1) ? g_hBhi : g_hAhi;
        u32* outlo = (l & 1) ? g_hBlo : g_hAlo;
        float cc0 = 0.f, cc1 = 0.f;

        for (int t = 0; t < TT; ++t) {
            float c[2][4];
            // pre-wait fetch of accumulator init (hides latency in barrier wait)
            if (l > 0) {
                const float* gw = gG0 + (size_t)t * 2048;
                const float2 v00 = *(const float2*)(gw + (mb + lr) * 32 + col0);
                const float2 v10 = *(const float2*)(gw + (mb + 8 + lr) * 32 + col0);
                const float2 v01 = *(const float2*)(gw + (mb + lr) * 32 + col0 + 8);
                const float2 v11 = *(const float2*)(gw + (mb + 8 + lr) * 32 + col0 + 8);
                c[0][0] = v00.x; c[0][1] = v00.y; c[0][2] = v10.x; c[0][3] = v10.y;
                c[1][0] = v01.x; c[1][1] = v01.y; c[1][2] = v11.x; c[1][3] = v11.y;
            } else {
                if (tid < 32) xs[tid] = p.x[(size_t)(b0 + tid) * TT + t];
            }

            if (t > 0) bar_wait(&bars[l * TT + t - 1], GRP);
            else       __syncthreads();

            if (t > 0) {
                load_B(outhi, outlo, t - 1, b0, sBhi, sBlo, wid, lane);
                __syncthreads();
            }

            if (l == 0) {
                const float w0 = wxs[mb + lr],     bv0 = bs0[mb + lr];
                const float w1 = wxs[mb + 8 + lr], bv1 = bs0[mb + 8 + lr];
                const float x00 = xs[col0], x01 = xs[col0 + 1];
                const float x10 = xs[col0 + 8], x11 = xs[col0 + 9];
                c[0][0] = fmaf(w0, x00, bv0); c[0][1] = fmaf(w0, x01, bv0);
                c[0][2] = fmaf(w1, x00, bv1); c[0][3] = fmaf(w1, x01, bv1);
                c[1][0] = fmaf(w0, x10, bv0); c[1][1] = fmaf(w0, x11, bv0);
                c[1][2] = fmaf(w1, x10, bv1); c[1][3] = fmaf(w1, x11, bv1);
            }

            if (t > 0) mma_full(aHH_hi, aHH_lo, bAd_hi, bAd_lo, c);

            // gates -> smem
            gsm[(mb + lr) * GS + col0]         = c[0][0];
            gsm[(mb + lr) * GS + col0 + 1]     = c[0][1];
            gsm[(mb + 8 + lr) * GS + col0]     = c[0][2];
            gsm[(mb + 8 + lr) * GS + col0 + 1] = c[0][3];
            gsm[(mb + lr) * GS + col0 + 8]     = c[1][0];
            gsm[(mb + lr) * GS + col0 + 9]     = c[1][1];
            gsm[(mb + 8 + lr) * GS + col0 + 8] = c[1][2];
            gsm[(mb + 8 + lr) * GS + col0 + 9] = c[1][3];
            __syncthreads();

            // elementwise LSTM cell for owned hidden pair x batch col
            {
                const int jl0 = 2 * jp, jl1 = jl0 + 1;
                const float ig0 = gsm[jl0 * GS + bbx];
                const float fg0 = gsm[(16 + jl0) * GS + bbx];
                const float gg0 = gsm[(32 + jl0) * GS + bbx];
                const float og0 = gsm[(48 + jl0) * GS + bbx];
                const float ig1 = gsm[jl1 * GS + bbx];
                const float fg1 = gsm[(16 + jl1) * GS + bbx];
                const float gg1 = gsm[(32 + jl1) * GS + bbx];
                const float og1 = gsm[(48 + jl1) * GS + bbx];

                cc0 = sigf(fg0) * cc0 + sigf(ig0) * tanhfast(gg0);
                cc1 = sigf(fg1) * cc1 + sigf(ig1) * tanhfast(gg1);
                const float h0 = sigf(og0) * tanhfast(cc0);
                const float h1 = sigf(og1) * tanhfast(cc1);

                u32 hiw, low;
                split_pack(h0, h1, hiw, low);
                const size_t wi = ((size_t)t * BB + b0 + bbx) * 128 + (j0 >> 1) + jp;
                outhi[wi] = hiw;
                outlo[wi] = low;
            }

            bar_arrive(&bars[l * TT + t]);

            // fused input projection for layer l+1 on h_l(t-1), hidden in barrier window
            if (l < 3 && t > 0) {
                float c2[2][4];
                const float bn0 = bsn[mb + lr], bn1 = bsn[mb + 8 + lr];
                c2[0][0] = bn0; c2[0][1] = bn0; c2[0][2] = bn1; c2[0][3] = bn1;
                c2[1][0] = bn0; c2[1][1] = bn0; c2[1][2] = bn1; c2[1][3] = bn1;
                mma_full(aIH_hi, aIH_lo, bAd_hi, bAd_lo, c2);
                float* gw = gG0 + (size_t)(t - 1) * 2048;
                *(float2*)(gw + (mb + lr) * 32 + col0)         = make_float2(c2[0][0], c2[0][1]);
                *(float2*)(gw + (mb + 8 + lr) * 32 + col0)     = make_float2(c2[0][2], c2[0][3]);
                *(float2*)(gw + (mb + lr) * 32 + col0 + 8)     = make_float2(c2[1][0], c2[1][1]);
                *(float2*)(gw + (mb + 8 + lr) * 32 + col0 + 8) = make_float2(c2[1][2], c2[1][3]);
            }
        }

        if (l < 3) {
            // produce gih_{l+1}[T-1] from h_l(T-1)
            bar_wait(&bars[l * TT + TT - 1], GRP);
            load_B(outhi, outlo, TT - 1, b0, sBhi, sBlo, wid, lane);
            __syncthreads();
            {
                float c2[2][4];
                const float bn0 = bsn[mb + lr], bn1 = bsn[mb + 8 + lr];
                c2[0][0] = bn0; c2[0][1] = bn0; c2[0][2] = bn1; c2[0][3] = bn1;
                c2[1][0] = bn0; c2[1][1] = bn0; c2[1][2] = bn1; c2[1][3] = bn1;
                mma_full(aIH_hi, aIH_lo, bAd_hi, bAd_lo, c2);
                float* gw = gG0 + (size_t)(TT - 1) * 2048;
                *(float2*)(gw + (mb + lr) * 32 + col0)         = make_float2(c2[0][0], c2[0][1]);
                *(float2*)(gw + (mb + 8 + lr) * 32 + col0)     = make_float2(c2[0][2], c2[0][3]);
                *(float2*)(gw + (mb + lr) * 32 + col0 + 8)     = make_float2(c2[1][0], c2[1][1]);
                *(float2*)(gw + (mb + 8 + lr) * 32 + col0 + 8) = make_float2(c2[1][2], c2[1][3]);
            }
            __syncthreads();
            // stage next layer weights
            load_W(p.Whh[l + 1], j0, sAhhHi, sAhhLo);
            if (l + 2 < LL) {
                load_W(p.Wih[l + 2], j0, sAihHi, sAihLo);
                if (tid < 64) {
                    const int row = (tid >> 4) * HH + j0 + (tid & 15);
                    bsn[tid] = p.bih[l + 2][row] + p.bhh[l + 2][row];
                }
            }
            __syncthreads();
        }
    }

    // signal completion
    __syncthreads();
    if (tid == 0) {
        asm volatile("red.release.gpu.global.add.u32 [%0], %1;"
                     :: "l"(&g_fin), "r"(1u) : "memory");
    }

    // block 0: wait for everyone, FC on h_3(T-1), reset barrier state
    if (bid == 0) {
        if (tid == 0) {
            unsigned v;
            asm volatile("ld.acquire.gpu.global.u32 %0, [%1];" : "=r"(v) : "l"(&g_fin) : "memory");
            while (v < (unsigned)NBLK) {
                __nanosleep(64);
                asm volatile("ld.acquire.gpu.global.u32 %0, [%1];" : "=r"(v) : "l"(&g_fin) : "memory");
            }
        }
        __syncthreads();

        const int b = tid;   // 256 threads = 256 batch rows
        float acc = p.fcb[0];
        const u32* bh = g_hBhi + ((size_t)(TT - 1) * BB + b) * 128;
        const u32* bl = g_hBlo + ((size_t)(TT - 1) * BB + b) * 128;
        #pragma unroll 4
        for (int k2 = 0; k2 < 128; ++k2) {
            const u32 hw = bh[k2];
            const u32 lw = bl[k2];
            const __nv_bfloat162 h2 = *reinterpret_cast<const __nv_bfloat162*>(&hw);
            const __nv_bfloat162 l2 = *reinterpret_cast<const __nv_bfloat162*>(&lw);
            const float h0 = __bfloat162float(h2.x) + __bfloat162float(l2.x);
            const float h1 = __bfloat162float(h2.y) + __bfloat162float(l2.y);
            const float2 w = *(const float2*)(p.fcW + 2 * k2);
            acc = fmaf(w.x, h0, fmaf(w.y, h1, acc));
        }
        p.out[b] = acc;

        for (int i = tid; i < 8 * LL * TT; i += NTHR) g_bar[i] = 0;
        if (tid == 0) g_fin = 0;
        __threadfence();
    }
}

extern "C" void kernel_launch(void* const* d_in, const int* in_sizes, int n_in,
                              void* d_out, int out_size) {
    (void)in_sizes; (void)n_in; (void)out_size;
    Params p;
    p.x = (const float*)d_in[0];
    for (int l = 0; l < LL; ++l) {
        p.Wih[l] = (const float*)d_in[1 + 4 * l];
        p.Whh[l] = (const float*)d_in[2 + 4 * l];
        p.bih[l] = (const float*)d_in[3 + 4 * l];
        p.bhh[l] = (const float*)d_in[4 + 4 * l];
    }
    p.fcW = (const float*)d_in[17];
    p.fcb = (const float*)d_in[18];
    p.out = (float*)d_out;

    cudaFuncSetAttribute(lstm_fused, cudaFuncAttributeMaxDynamicSharedMemorySize, SMEM_BYTES);
    lstm_fused<<<NBLK, NTHR, SMEM_BYTES>>>(p);
}